// round 10
// baseline (speedup 1.0000x reference)
#include <cuda_runtime.h>
#include <cuda_bf16.h>
#include <cstdint>

// Problem constants (fixed by setup_inputs)
#define BB 4
#define CC 128
#define HH 512
#define WW 512
#define HWPX (HH * WW)          // 262144 pixels per image
#define NT 800                  // n_tokens
#define ML 1024                 // max_length
#define NSEG (BB * NT)          // 3200
#define NCLS 5

// Output layout (concatenated f32): tokens [B,ML,C] | labels [B,ML] | pads [B,1]
#define TOK_ELEMS ((size_t)BB * ML * CC)   // 524288
#define LAB_OFF   TOK_ELEMS
#define PAD_OFF   (TOK_ELEMS + (size_t)BB * ML)

// Global accumulator, layout [quarter][image][800][32]  (NSEG*CC floats)
// Zero-initialized at module load; k4_final re-zeroes after reading, so every
// graph replay sees zeros (no separate init kernel).
__device__ __align__(1024) float g_accum[NSEG * CC];
__device__ int g_hist[NSEG * NCLS];

// ---------------------------------------------------------------------------
// Main pass: grid (37, B, 4); z = channel quarter (32 ch). 592 CTAs = 4 waves,
// 1 CTA/SM (~169 KB smem), 512 threads (16 warps).
// CTA-private smem accumulator acc[800][32] (100 KB). No data atomics:
// warp w exclusively owns segments with (s & 15) == w (ballot+shfl combine;
// 1 lane = 1 channel -> 3 smem ops per owned pixel).
// 4-deep cp.async pipeline of 128px x 32ch subtiles (16 KB each, pitch 129):
//   cp.async 4B scalar, warp-contiguous 128B -> coalesced
//   tile LDS bank (l+p)%32 ✓ ; acc bank l ✓
// One commit per round (empty commits in the tail keep wait_group exact).
// End: per-warp 6400B TMA bulk-reduce flush into L2-resident g_accum.
// ---------------------------------------------------------------------------
#define QCH 32                          // channels per CTA
#define PX 128                          // pixels per subtile
#define NSUB (HWPX / PX)                // 2048
#define NCTA 37
#define ACC_FLOATS (NT * QCH)           // 25600
#define TPITCH 129
#define TILE_FLOATS (QCH * TPITCH)      // 4128
#define NBUF 4
#define SMEM_BYTES ((ACC_FLOATS + NBUF * TILE_FLOATS) * 4 + NBUF * PX * 8)

#define CP4(dst, src)                                                        \
    asm volatile("cp.async.ca.shared.global [%0], [%1], 4;"                  \
                 :: "r"((uint32_t)__cvta_generic_to_shared(dst)),            \
                    "l"(src) : "memory")

__global__ __launch_bounds__(512) void k_pass(const float* __restrict__ F,
                                              const int* __restrict__ seg,
                                              const int* __restrict__ gts) {
    extern __shared__ float smem[];
    float* acc     = smem;                                   // [800][32]
    float* tilebuf = acc + ACC_FLOATS;                       // NBUF x [32][129]
    int*   sseg    = (int*)(tilebuf + NBUF * TILE_FLOATS);   // NBUF x [128]
    int*   sgts    = sseg + NBUF * PX;                       // NBUF x [128]

    int b   = blockIdx.y;
    int q   = blockIdx.z;                       // channel quarter
    int cta = blockIdx.x;                       // 0..36
    int t   = threadIdx.x;
    int w   = t >> 5;
    int l   = t & 31;

    for (int i = t; i < ACC_FLOATS; i += 512) acc[i] = 0.f;
    __syncthreads();

    const float* Fq   = F + ((size_t)b * CC + (size_t)q * QCH) * HWPX;
    const int*   segb = seg + (size_t)b * HWPX;
    const int*   gtsb = gts + (size_t)b * HWPX;

    // issue subtile st into buffer buf (or just an empty commit)
    auto issue = [&](int st, int buf) {
        if (st < NSUB) {
            int p0 = st * PX;
            float* tile = tilebuf + buf * TILE_FLOATS;
            if (t < PX) {
                CP4(&sseg[buf * PX + t], segb + p0 + t);
                if (q == 0) CP4(&sgts[buf * PX + t], gtsb + p0 + t);
            }
#pragma unroll
            for (int j = 0; j < 2; j++) {
                int c = (t >> 5) + (j << 4);            // 16 warps x 2 = 32 ch
#pragma unroll
                for (int i = 0; i < 4; i++) {
                    int p = l + (i << 5);
                    CP4(&tile[c * TPITCH + p], Fq + (size_t)c * HWPX + p0 + p);
                }
            }
        }
        asm volatile("cp.async.commit_group;" ::: "memory");
    };

    // combine buffer buf into the private accumulator (no atomics)
    auto accum = [&](int buf) {
        const float* tile = tilebuf + buf * TILE_FLOATS;
        const int*   ss   = sseg + buf * PX;
#pragma unroll
        for (int chunk = 0; chunk < 4; chunk++) {
            int P0 = chunk << 5;
            int myseg = ss[P0 + l];                     // conflict-free LDS
            if (q == 0 && w == 12 + chunk)              // hist on warps 12-15
                atomicAdd(&g_hist[(myseg + b * NT) * NCLS +
                                  sgts[buf * PX + P0 + l]], 1);
            unsigned mask = __ballot_sync(0xffffffffu, (myseg & 15) == w);
            while (mask) {
                int p = __ffs(mask) - 1;
                mask &= mask - 1;
                int s = __shfl_sync(0xffffffffu, myseg, p);
                float v = tile[l * TPITCH + P0 + p];    // bank (l+p)%32
                acc[s * QCH + l] += v;                  // bank l, exclusive
            }
        }
    };

    // prologue: fill the 4-deep pipeline
#pragma unroll
    for (int j = 0; j < NBUF; j++) issue(cta + j * NCTA, j);

    int k = 0;
    for (int st = cta; st < NSUB; st += NCTA, k++) {
        int buf = k % NBUF;
        asm volatile("cp.async.wait_group %0;" :: "n"(NBUF - 1) : "memory");
        __syncthreads();                    // tile[buf] fully resident
        accum(buf);
        __syncthreads();                    // everyone done reading buf
        issue(st + NBUF * NCTA, buf);       // refill (or empty commit)
    }
    asm volatile("cp.async.wait_group 0;" ::: "memory");
    __syncthreads();

    // ---- flush: TMA bulk-reduce the private accumulator into g_accum ----
    asm volatile("fence.proxy.async.shared::cta;" ::: "memory");
    if (l == 0) {
        float* dst = g_accum + ((size_t)(q * BB + b) * NT) * QCH + (size_t)w * 1600;
        uint32_t src = (uint32_t)__cvta_generic_to_shared(acc + w * 1600);
        asm volatile(
            "cp.reduce.async.bulk.global.shared::cta.bulk_group.add.f32 "
            "[%0], [%1], %2;"
            :: "l"(dst), "r"(src), "r"(6400) : "memory");
        asm volatile("cp.async.bulk.commit_group;" ::: "memory");
        asm volatile("cp.async.bulk.wait_group 0;" ::: "memory");
    }
}

// ---------------------------------------------------------------------------
// K4: finalize. Block per (b, sl): mean, mode, padding, pads.
// g_accum layout [q][b][sl][c32] -> output position t = q*32 + c32.
// Re-zeroes g_accum / g_hist after reading (init for the next graph replay).
// ---------------------------------------------------------------------------
__global__ __launch_bounds__(128) void k4_final(float* __restrict__ out) {
    int b  = blockIdx.y;
    int sl = blockIdx.x;
    int t  = threadIdx.x;

    float* tok = out + ((size_t)b * ML + sl) * CC;

    if (sl >= NT) {                       // padding region
        tok[t] = 0.f;
        if (t == 0) out[LAB_OFF + (size_t)b * ML + sl] = 0.f;
        return;
    }

    int s = b * NT + sl;

    __shared__ int s_cnt;
    if (t == 0) {
        int hh[NCLS], cnt = 0;
#pragma unroll
        for (int c = 0; c < NCLS; c++) {
            hh[c] = g_hist[s * NCLS + c];
            g_hist[s * NCLS + c] = 0;               // re-init for next replay
            cnt += hh[c];
        }
        int best = 0, bc = hh[0];
#pragma unroll
        for (int c = 1; c < NCLS; c++) if (hh[c] > bc) { bc = hh[c]; best = c; }
        out[LAB_OFF + (size_t)b * ML + sl] = (float)best;
        if (sl == 0) out[PAD_OFF + b] = (float)(ML - NT);
        s_cnt = cnt;
    }
    __syncthreads();

    int cnt = s_cnt;
    float inv = 1.f / (float)(cnt > 0 ? cnt : 1);
    int q = t >> 5, c = t & 31;
    size_t idx = (((size_t)(q * BB + b) * NT) + sl) * QCH + c;
    float v = g_accum[idx];
    g_accum[idx] = 0.f;                             // re-init for next replay
    tok[t] = v * inv;
}

// ---------------------------------------------------------------------------
extern "C" void kernel_launch(void* const* d_in, const int* in_sizes, int n_in,
                              void* d_out, int out_size) {
    const float* features = (const float*)d_in[0];
    const int*   gts      = (const int*)d_in[1];
    const int*   segments = (const int*)d_in[2];
    float*       out      = (float*)d_out;

    (void)in_sizes; (void)n_in; (void)out_size;

    static bool attr_set = false;
    if (!attr_set) {
        cudaFuncSetAttribute(k_pass, cudaFuncAttributeMaxDynamicSharedMemorySize,
                             SMEM_BYTES);
        attr_set = true;
    }

    {
        dim3 g(NCTA, BB, 4);               // 592 CTAs = 4 waves
        k_pass<<<g, 512, SMEM_BYTES>>>(features, segments, gts);
    }
    {
        dim3 g(ML, BB);                    // (1024, 4)
        k4_final<<<g, 128>>>(out);
    }
}

// round 11
// speedup vs baseline: 1.2826x; 1.2826x over previous
#include <cuda_runtime.h>
#include <cuda_bf16.h>
#include <cstdint>

// Problem constants (fixed by setup_inputs)
#define BB 4
#define CC 128
#define HH 512
#define WW 512
#define HWPX (HH * WW)          // 262144 pixels per image
#define NT 800                  // n_tokens
#define ML 1024                 // max_length
#define NSEG (BB * NT)          // 3200
#define NCLS 5

// Output layout (concatenated f32): tokens [B,ML,C] | labels [B,ML] | pads [B,1]
#define TOK_ELEMS ((size_t)BB * ML * CC)   // 524288
#define LAB_OFF   TOK_ELEMS
#define PAD_OFF   (TOK_ELEMS + (size_t)BB * ML)

// Global accumulator, layout [quarter][image][800][32]
__device__ __align__(1024) float g_accum[NSEG * CC];
__device__ int g_hist[NSEG * NCLS];

// ---------------------------------------------------------------------------
// K1: zero accumulators + histograms (vectorized)
// ---------------------------------------------------------------------------
__global__ __launch_bounds__(512) void k1_init() {
    int i = blockIdx.x * blockDim.x + threadIdx.x;
    if (i < NSEG * CC / 4) ((float4*)g_accum)[i] = make_float4(0.f,0.f,0.f,0.f);
    if (i < NSEG * NCLS) g_hist[i] = 0;
}

// ---------------------------------------------------------------------------
// Main pass: grid (37, B, 4); z = channel quarter (32 ch -> 1 lane = 1 ch).
// 592 CTAs = 4 waves, 1 CTA/SM (~178 KB smem), 512 threads (16 warps).
// CTA-private smem accumulator acc[800][32]. No data atomics.
// Combine is DE-SERIALIZED: per 32-px chunk, ballot ownership
// ((s & 15) == w), popc-prefix compact owned pixels into a per-warp smem
// list, then an unrolled-by-2 loop accumulates list entries — independent
// iterations, pipelined; no ffs/shfl dependency chain.
// Banks: tile pixel-major pitch 33 -> CP4 dst (p+c)%32 ✓, combine read
// (p+l)%32 ✓; acc bank l ✓; list writes compacted-consecutive ✓.
// 4-deep cp.async pipeline; one commit per round (empty commits in tail).
// End: per-warp 6400B TMA bulk-reduce flush into L2-resident g_accum.
// ---------------------------------------------------------------------------
#define QCH 32
#define PX 128
#define NSUB (HWPX / PX)                // 2048
#define NCTA 37
#define ACC_FLOATS (NT * QCH)           // 25600
#define TPITCH 33
#define TILE_FLOATS (PX * TPITCH)       // 4224
#define NBUF 4
#define SMEM_BYTES ((ACC_FLOATS + NBUF * TILE_FLOATS + NBUF * PX * 2 + 16 * PX) * 4)

#define CP4(dst, src)                                                        \
    asm volatile("cp.async.ca.shared.global [%0], [%1], 4;"                  \
                 :: "r"((uint32_t)__cvta_generic_to_shared(dst)),            \
                    "l"(src) : "memory")

__global__ __launch_bounds__(512) void k_pass(const float* __restrict__ F,
                                              const int* __restrict__ seg,
                                              const int* __restrict__ gts) {
    extern __shared__ float smem[];
    float* acc     = smem;                                   // [800][32]
    float* tilebuf = acc + ACC_FLOATS;                       // NBUF x [128][33]
    int*   sseg    = (int*)(tilebuf + NBUF * TILE_FLOATS);   // NBUF x [128]
    int*   sgts    = sseg + NBUF * PX;                       // NBUF x [128]
    int*   wlist   = sgts + NBUF * PX;                       // [16][128]

    int b   = blockIdx.y;
    int q   = blockIdx.z;
    int cta = blockIdx.x;                       // 0..36
    int t   = threadIdx.x;
    int w   = t >> 5;
    int l   = t & 31;

    for (int i = t; i < ACC_FLOATS; i += 512) acc[i] = 0.f;
    __syncthreads();

    const float* Fq   = F + ((size_t)b * CC + (size_t)q * QCH) * HWPX;
    const int*   segb = seg + (size_t)b * HWPX;
    const int*   gtsb = gts + (size_t)b * HWPX;

    // issue subtile st into buffer buf (or just an empty commit)
    auto issue = [&](int st, int buf) {
        if (st < NSUB) {
            int p0 = st * PX;
            float* tile = tilebuf + buf * TILE_FLOATS;
            if (t < PX) {
                CP4(&sseg[buf * PX + t], segb + p0 + t);
                if (q == 0) CP4(&sgts[buf * PX + t], gtsb + p0 + t);
            }
            // warp w loads channels w and w+16; pixel-major scatter into tile
#pragma unroll
            for (int j = 0; j < 2; j++) {
                int c = w + (j << 4);
                const float* src = Fq + (size_t)c * HWPX + p0;
#pragma unroll
                for (int i = 0; i < 4; i++) {
                    int p = (i << 5) + l;
                    CP4(&tile[p * TPITCH + c], src + p);  // bank (p+c)%32 ✓
                }
            }
        }
        asm volatile("cp.async.commit_group;" ::: "memory");
    };

    // combine buffer buf into the private accumulator
    auto accum = [&](int buf) {
        const float* tile = tilebuf + buf * TILE_FLOATS;
        const int*   ss   = sseg + buf * PX;

        // histogram: warps 12..15 cover the 4 chunks (fire-and-forget RED)
        if (q == 0 && w >= 12) {
            int p  = ((w - 12) << 5) + l;
            atomicAdd(&g_hist[(ss[p] + b * NT) * NCLS + sgts[buf * PX + p]], 1);
        }

        // phase 1: ballot + popc-prefix compaction into per-warp list
        int cnt = 0;
#pragma unroll
        for (int chunk = 0; chunk < 4; chunk++) {
            int p = (chunk << 5) + l;
            int s = ss[p];                              // bank l ✓
            bool own = (s & 15) == w;
            unsigned m = __ballot_sync(0xffffffffu, own);
            if (own) {
                int idx = cnt + __popc(m & ((1u << l) - 1u));
                wlist[(w << 7) + idx] = (s * QCH) | (p << 16);
            }
            cnt += __popc(m);
        }

        // phase 2: accumulate list entries (unrolled by 2 -> parallel chains)
        int i = 0;
        for (; i + 2 <= cnt; i += 2) {
            int e0 = wlist[(w << 7) + i];
            int e1 = wlist[(w << 7) + i + 1];
            float v0 = tile[(e0 >> 16) * TPITCH + l];   // bank (p+l)%32 ✓
            float v1 = tile[(e1 >> 16) * TPITCH + l];
            acc[(e0 & 0xffff) + l] += v0;               // bank l ✓ exclusive
            acc[(e1 & 0xffff) + l] += v1;
        }
        if (i < cnt) {
            int e = wlist[(w << 7) + i];
            acc[(e & 0xffff) + l] += tile[(e >> 16) * TPITCH + l];
        }
    };

    // prologue: fill the 4-deep pipeline
#pragma unroll
    for (int j = 0; j < NBUF; j++) issue(cta + j * NCTA, j);

    int k = 0;
    for (int st = cta; st < NSUB; st += NCTA, k++) {
        int buf = k & (NBUF - 1);
        asm volatile("cp.async.wait_group %0;" :: "n"(NBUF - 1) : "memory");
        __syncthreads();                    // tile[buf] fully resident
        accum(buf);
        __syncthreads();                    // everyone done reading buf
        issue(st + NBUF * NCTA, buf);       // refill (or empty commit)
    }
    asm volatile("cp.async.wait_group 0;" ::: "memory");
    __syncthreads();

    // ---- flush: TMA bulk-reduce the private accumulator into g_accum ----
    asm volatile("fence.proxy.async.shared::cta;" ::: "memory");
    if (l == 0) {
        float* dst = g_accum + ((size_t)(q * BB + b) * NT) * QCH + (size_t)w * 1600;
        uint32_t src = (uint32_t)__cvta_generic_to_shared(acc + w * 1600);
        asm volatile(
            "cp.reduce.async.bulk.global.shared::cta.bulk_group.add.f32 "
            "[%0], [%1], %2;"
            :: "l"(dst), "r"(src), "r"(6400) : "memory");
        asm volatile("cp.async.bulk.commit_group;" ::: "memory");
        asm volatile("cp.async.bulk.wait_group 0;" ::: "memory");
    }
}

// ---------------------------------------------------------------------------
// K4: finalize. Block per (b, sl): mean, mode, padding, pads.
// g_accum layout [q][b][sl][c32] -> output position t = q*32 + c32.
// ---------------------------------------------------------------------------
__global__ __launch_bounds__(128) void k4_final(float* __restrict__ out) {
    int b  = blockIdx.y;
    int sl = blockIdx.x;
    int t  = threadIdx.x;

    float* tok = out + ((size_t)b * ML + sl) * CC;

    if (sl >= NT) {                       // padding region
        tok[t] = 0.f;
        if (t == 0) out[LAB_OFF + (size_t)b * ML + sl] = 0.f;
        return;
    }

    int s = b * NT + sl;

    __shared__ int s_cnt;
    if (t == 0) {
        int hh[NCLS], cnt = 0;
#pragma unroll
        for (int c = 0; c < NCLS; c++) { hh[c] = g_hist[s * NCLS + c]; cnt += hh[c]; }
        int best = 0, bc = hh[0];
#pragma unroll
        for (int c = 1; c < NCLS; c++) if (hh[c] > bc) { bc = hh[c]; best = c; }
        out[LAB_OFF + (size_t)b * ML + sl] = (float)best;
        if (sl == 0) out[PAD_OFF + b] = (float)(ML - NT);
        s_cnt = cnt;
    }
    __syncthreads();

    int cnt = s_cnt;
    float inv = 1.f / (float)(cnt > 0 ? cnt : 1);
    int q = t >> 5, c = t & 31;
    float v = g_accum[(((size_t)(q * BB + b) * NT) + sl) * QCH + c];
    tok[t] = v * inv;
}

// ---------------------------------------------------------------------------
extern "C" void kernel_launch(void* const* d_in, const int* in_sizes, int n_in,
                              void* d_out, int out_size) {
    const float* features = (const float*)d_in[0];
    const int*   gts      = (const int*)d_in[1];
    const int*   segments = (const int*)d_in[2];
    float*       out      = (float*)d_out;

    (void)in_sizes; (void)n_in; (void)out_size;

    static bool attr_set = false;
    if (!attr_set) {
        cudaFuncSetAttribute(k_pass, cudaFuncAttributeMaxDynamicSharedMemorySize,
                             SMEM_BYTES);
        attr_set = true;
    }

    k1_init<<<(NSEG * CC / 4 + 511) / 512, 512>>>();
    {
        dim3 g(NCTA, BB, 4);               // 592 CTAs = 4 waves
        k_pass<<<g, 512, SMEM_BYTES>>>(features, segments, gts);
    }
    {
        dim3 g(ML, BB);                    // (1024, 4)
        k4_final<<<g, 128>>>(out);
    }
}

// round 13
// speedup vs baseline: 1.6493x; 1.2859x over previous
#include <cuda_runtime.h>
#include <cuda_bf16.h>
#include <cstdint>

// Problem constants (fixed by setup_inputs)
#define BB 4
#define CC 128
#define HH 512
#define WW 512
#define HWPX (HH * WW)          // 262144 pixels per image
#define NT 800                  // n_tokens
#define ML 1024                 // max_length
#define NSEG (BB * NT)          // 3200
#define NCLS 5

// Output layout (concatenated f32): tokens [B,ML,C] | labels [B,ML] | pads [B,1]
#define TOK_ELEMS ((size_t)BB * ML * CC)   // 524288
#define LAB_OFF   TOK_ELEMS
#define PAD_OFF   (TOK_ELEMS + (size_t)BB * ML)

// Segment accumulators (1.6 MB, L2-resident) + class histograms.
// g_accum row position t holds channel (t&3)*32 + (t>>2) (un-permuted in k4).
__device__ __align__(1024) float g_accum[NSEG * CC];
__device__ int g_hist[NSEG * NCLS];

// ---------------------------------------------------------------------------
// K1: zero accumulators + histograms
// ---------------------------------------------------------------------------
__global__ __launch_bounds__(512) void k1_init() {
    int i = blockIdx.x * blockDim.x + threadIdx.x;
    if (i < NSEG * CC / 4) ((float4*)g_accum)[i] = make_float4(0.f,0.f,0.f,0.f);
    if (i < NSEG * NCLS) g_hist[i] = 0;
}

// ---------------------------------------------------------------------------
// K3: main pass. Block = 32 px x 128 ch, 256 threads, grid (8192, 4).
//  stage1: coalesced scalar LDG (channel-major) -> smem tile [c][p] pitch 33
//          STS bank (c+l)%32 conflict-free
//  stage2: lane l gathers channels {l,l+32,l+64,l+96} of pixel p
//          LDS bank (l+p)%32 conflict-free -> float4 in registers
//  reduce: ONE red.global.add.v4.f32 per pixel row, lanes consecutive ->
//          512B coalesced reduction into the L2-resident accumulator.
//          (RMW runs on the LTS atomic ALU, fire-and-forget, no tail wait.)
//  hist:   fused (1 global atomic per pixel, hidden under memory waits)
// ---------------------------------------------------------------------------
__global__ __launch_bounds__(256) void k3_main(const float* __restrict__ F,
                                               const int* __restrict__ seg,
                                               const int* __restrict__ gts) {
    __shared__ float tile[CC * 33];     // 16.9 KB
    __shared__ int   sseg[32];

    int b  = blockIdx.y;
    int p0 = blockIdx.x * 32;
    int t  = threadIdx.x;
    int w  = t >> 5;
    int l  = t & 31;

    if (t < 32) {
        int gi = b * HWPX + p0 + t;
        int s  = seg[gi] + b * NT;
        sseg[t] = s;
        atomicAdd(&g_hist[s * NCLS + gts[gi]], 1);
    }

    const float* Fb = F + (size_t)b * CC * HWPX + p0;
#pragma unroll
    for (int k = 0; k < 16; k++) {
        int c = (k << 3) + w;                       // channels 0..127
        tile[c * 33 + l] = Fb[(size_t)c * HWPX + l];
    }
    __syncthreads();

    // stage2 + reduce: warp w owns pixels 4w .. 4w+3
#pragma unroll
    for (int i = 0; i < 4; i++) {
        int p = (w << 2) + i;
        float4 v;
        v.x = tile[(l      ) * 33 + p];
        v.y = tile[(l +  32) * 33 + p];
        v.z = tile[(l +  64) * 33 + p];
        v.w = tile[(l +  96) * 33 + p];
        float* dst = g_accum + (size_t)sseg[p] * CC + (l << 2);
        asm volatile("red.global.add.v4.f32 [%0], {%1, %2, %3, %4};"
                     :: "l"(dst), "f"(v.x), "f"(v.y), "f"(v.z), "f"(v.w)
                     : "memory");
    }
}

// ---------------------------------------------------------------------------
// K4: finalize. Block per (b, sl): mean (channel un-permute), mode,
//     padding, pads. Counts derived from the histogram.
// ---------------------------------------------------------------------------
__global__ __launch_bounds__(128) void k4_final(float* __restrict__ out) {
    int b  = blockIdx.y;
    int sl = blockIdx.x;
    int t  = threadIdx.x;

    float* tok = out + ((size_t)b * ML + sl) * CC;

    if (sl >= NT) {                       // padding region
        tok[t] = 0.f;
        if (t == 0) out[LAB_OFF + (size_t)b * ML + sl] = 0.f;
        return;
    }

    int s = b * NT + sl;

    __shared__ int s_cnt;
    if (t == 0) {
        int hh[NCLS], cnt = 0;
#pragma unroll
        for (int c = 0; c < NCLS; c++) { hh[c] = g_hist[s * NCLS + c]; cnt += hh[c]; }
        int best = 0, bc = hh[0];
#pragma unroll
        for (int c = 1; c < NCLS; c++) if (hh[c] > bc) { bc = hh[c]; best = c; }
        out[LAB_OFF + (size_t)b * ML + sl] = (float)best;
        if (sl == 0) out[PAD_OFF + b] = (float)(ML - NT);
        s_cnt = cnt;
    }
    __syncthreads();

    int cnt = s_cnt;
    float inv = 1.f / (float)(cnt > 0 ? cnt : 1);
    float v = g_accum[(size_t)s * CC + t] * inv;
    int c = ((t & 3) << 5) + (t >> 2);    // storage position -> true channel
    tok[c] = v;
}

// ---------------------------------------------------------------------------
extern "C" void kernel_launch(void* const* d_in, const int* in_sizes, int n_in,
                              void* d_out, int out_size) {
    const float* features = (const float*)d_in[0];
    const int*   gts      = (const int*)d_in[1];
    const int*   segments = (const int*)d_in[2];
    float*       out      = (float*)d_out;

    (void)in_sizes; (void)n_in; (void)out_size;

    k1_init<<<(NSEG * CC / 4 + 511) / 512, 512>>>();
    {
        dim3 g(HWPX / 32, BB);             // (8192, 4)
        k3_main<<<g, 256>>>(features, segments, gts);
    }
    {
        dim3 g(ML, BB);                    // (1024, 4)
        k4_final<<<g, 128>>>(out);
    }
}

// round 15
// speedup vs baseline: 2.3365x; 1.4167x over previous
#include <cuda_runtime.h>
#include <cuda_bf16.h>
#include <cstdint>

// Problem constants (fixed by setup_inputs)
#define BB 4
#define CC 128
#define HH 512
#define WW 512
#define HWPX (HH * WW)          // 262144 pixels per image
#define NT 800                  // n_tokens
#define ML 1024                 // max_length
#define NSEG (BB * NT)          // 3200
#define NCLS 5

// Output layout (concatenated f32): tokens [B,ML,C] | labels [B,ML] | pads [B,1]
#define TOK_ELEMS ((size_t)BB * ML * CC)   // 524288
#define LAB_OFF   TOK_ELEMS
#define PAD_OFF   (TOK_ELEMS + (size_t)BB * ML)

// Segment accumulators (1.6 MB, L2-resident) + class histograms.
// g_accum row position t holds channel (t&3)*32 + (t>>2) (un-permuted in k4).
__device__ __align__(1024) float g_accum[NSEG * CC];
__device__ int g_hist[NSEG * NCLS];

// ---------------------------------------------------------------------------
// K3: main pass (proven R4 config). Block = 32 px x 128 ch, 256 threads.
//  stage1: coalesced scalar LDG (channel-major) -> smem tile [c][p] pitch 33
//          STS bank (c+l)%32 conflict-free
//  stage2: lane l gathers channels {l,l+32,l+64,l+96} of pixel p
//          LDS bank (l+p)%32 conflict-free; permuted 512B row via STS.128
//  reduce: TMA bulk-reduce add.f32 of each 512B row into the L2-resident
//          accumulator (RMW runs on the LTS atomic path, offloaded from SM)
//  hist:   fused (1 global atomic per pixel, hidden under memory waits)
// ---------------------------------------------------------------------------
__global__ __launch_bounds__(256) void k3_main(const float* __restrict__ F,
                                               const int* __restrict__ seg,
                                               const int* __restrict__ gts) {
    __shared__ float tile[CC * 33];                     // [c][p] 16.9 KB
    __shared__ __align__(16) float rows[32 * CC];       // [p][pos] 16 KB
    __shared__ int sseg[32];

    int b  = blockIdx.y;
    int p0 = blockIdx.x * 32;
    int t  = threadIdx.x;
    int w  = t >> 5;
    int l  = t & 31;

    if (t < 32) {
        int gi = b * HWPX + p0 + t;
        int s  = seg[gi] + b * NT;
        sseg[t] = s;
        atomicAdd(&g_hist[s * NCLS + gts[gi]], 1);      // fused stats pass
    }

    const float* Fb = F + (size_t)b * CC * HWPX + p0;
#pragma unroll
    for (int k = 0; k < 16; k++) {
        int c = (k << 3) + w;                           // channels 0..127
        tile[c * 33 + l] = Fb[(size_t)c * HWPX + l];
    }
    __syncthreads();

    // stage2: warp w owns pixels 4w .. 4w+3
#pragma unroll
    for (int i = 0; i < 4; i++) {
        int p = (w << 2) + i;
        float4 v;
        v.x = tile[(l      ) * 33 + p];
        v.y = tile[(l +  32) * 33 + p];
        v.z = tile[(l +  64) * 33 + p];
        v.w = tile[(l +  96) * 33 + p];
        *(float4*)&rows[p * CC + (l << 2)] = v;
    }
    __syncwarp();
    asm volatile("fence.proxy.async.shared::cta;" ::: "memory");

    if (l == 0) {
#pragma unroll
        for (int i = 0; i < 4; i++) {
            int p = (w << 2) + i;
            float* dst = g_accum + (size_t)sseg[p] * CC;
            uint32_t src = (uint32_t)__cvta_generic_to_shared(&rows[p * CC]);
            asm volatile(
                "cp.reduce.async.bulk.global.shared::cta.bulk_group.add.f32 "
                "[%0], [%1], %2;"
                :: "l"(dst), "r"(src), "r"(512) : "memory");
        }
        asm volatile("cp.async.bulk.commit_group;" ::: "memory");
        asm volatile("cp.async.bulk.wait_group 0;" ::: "memory");
    }
}

// ---------------------------------------------------------------------------
// K4: finalize. 512 threads = 4 token-groups of 128; grid (256, 4).
// Mean (channel un-permute), mode, padding, pads.
// ---------------------------------------------------------------------------
__global__ __launch_bounds__(512) void k4_final(float* __restrict__ out) {
    int b  = blockIdx.y;
    int g  = threadIdx.x >> 7;                  // token-group 0..3
    int sl = (blockIdx.x << 2) + g;
    int t  = threadIdx.x & 127;

    float* tok = out + ((size_t)b * ML + sl) * CC;

    if (sl >= NT) {                       // padding region
        tok[t] = 0.f;
        if (t == 0) out[LAB_OFF + (size_t)b * ML + sl] = 0.f;
        return;
    }

    int s = b * NT + sl;

    __shared__ int s_cnt[4];
    if (t == 0) {
        int hh[NCLS], cnt = 0;
#pragma unroll
        for (int c = 0; c < NCLS; c++) { hh[c] = g_hist[s * NCLS + c]; cnt += hh[c]; }
        int best = 0, bc = hh[0];
#pragma unroll
        for (int c = 1; c < NCLS; c++) if (hh[c] > bc) { bc = hh[c]; best = c; }
        out[LAB_OFF + (size_t)b * ML + sl] = (float)best;
        if (sl == 0) out[PAD_OFF + b] = (float)(ML - NT);
        s_cnt[g] = cnt;
    }
    __syncwarp(0xffffffffu);
    // group-local broadcast: warps of group g read s_cnt[g] after leader wrote.
    // leader is lane 0 of the group's first warp; other warps may race ahead,
    // so use a group-scoped named barrier (128 threads each).
    asm volatile("bar.sync %0, 128;" :: "r"(g + 1) : "memory");

    int cnt = s_cnt[g];
    float inv = 1.f / (float)(cnt > 0 ? cnt : 1);
    float v = g_accum[(size_t)s * CC + t] * inv;
    int c = ((t & 3) << 5) + (t >> 2);    // storage position -> true channel
    tok[c] = v;
}

// ---------------------------------------------------------------------------
extern "C" void kernel_launch(void* const* d_in, const int* in_sizes, int n_in,
                              void* d_out, int out_size) {
    const float* features = (const float*)d_in[0];
    const int*   gts      = (const int*)d_in[1];
    const int*   segments = (const int*)d_in[2];
    float*       out      = (float*)d_out;

    (void)in_sizes; (void)n_in; (void)out_size;

    // Resolve scratch symbol addresses once (host-side, deterministic).
    static void* accum_ptr = nullptr;
    static void* hist_ptr  = nullptr;
    if (!accum_ptr) {
        cudaGetSymbolAddress(&accum_ptr, g_accum);
        cudaGetSymbolAddress(&hist_ptr,  g_hist);
    }

    // init via memset nodes (cheaper than a kernel launch)
    cudaMemsetAsync(accum_ptr, 0, NSEG * CC * sizeof(float), 0);
    cudaMemsetAsync(hist_ptr,  0, NSEG * NCLS * sizeof(int), 0);

    {
        dim3 g(HWPX / 32, BB);             // (8192, 4)
        k3_main<<<g, 256>>>(features, segments, gts);
    }
    {
        dim3 g(ML / 4, BB);                // (256, 4)
        k4_final<<<g, 512>>>(out);
    }
}